// round 3
// baseline (speedup 1.0000x reference)
#include <cuda_runtime.h>
#include <math.h>

#define BB 4
#define SS 2048
#define VV 64
#define DD 1024
#define PP 8
#define HH 42
#define KK 49152
#define EPSF 1e-12f
#define COSEPS 1e-8f
#define SQRT_S 45.254834f   // sqrt(2048)
#define NSC 64              // s-chunks in kavp (32 s each)

// ---------------- scratch (static device globals; no allocs allowed) ----------------
__device__ float g_u[PP * DD];              // sign-ish vectors e/max(2|e|,eps)
__device__ float g_w1t[HH * DD];            // w1 transposed [H][D]
__device__ float g_n[PP * BB * SS];         // n values
__device__ float g_wsm[PP * BB * SS];       // softmax weights over s
__device__ float g_avp[NSC * PP * BB * DD]; // a_v partials per s-chunk (8MB)
__device__ float g_av[PP * BB * DD];        // a_v
__device__ float g_gate[BB * PP];           // final gates
__device__ float g_htab[PP * VV * HH];      // tanh(tables@w1+b1) table [512][42]
__device__ float g_hbar[BB * VV * HH];      // gate-combined hidden

// ---------------- kernel 0: prep (u, w1 transpose) ----------------
__global__ void kprep(const float* __restrict__ lora, const float* __restrict__ w1) {
    int i = blockIdx.x * 256 + threadIdx.x;   // grid covers 43008 exactly
    if (i < PP * DD) {
        float e = lora[i];
        g_u[i] = e / fmaxf(2.0f * fabsf(e), EPSF);
    }
    if (i < HH * DD) {
        int h = i / DD, d = i % DD;
        g_w1t[i] = w1[d * HH + h];
    }
}

// ---------------- kernel 1: per-(b,s) row norm + 8 dots -> n[p,b,s] ----------------
__global__ __launch_bounds__(256) void knorm(const float* __restrict__ ctx) {
    __shared__ float s_u[PP * DD];
    for (int i = threadIdx.x; i < PP * DD; i += 256) s_u[i] = g_u[i];
    __syncthreads();
    int warp = threadIdx.x >> 5, lane = threadIdx.x & 31;
    int row = blockIdx.x * 8 + warp;          // [0, B*S)
    int b = row / SS, s = row % SS;
    const float4* x4 = reinterpret_cast<const float4*>(ctx + (size_t)row * DD);
    float nrm2 = 0.f;
    float dot[PP];
#pragma unroll
    for (int p = 0; p < PP; p++) dot[p] = 0.f;
#pragma unroll
    for (int it = 0; it < 8; it++) {
        int q = lane + it * 32;               // float4 index 0..255
        float4 x = x4[q];
        nrm2 += x.x * x.x + x.y * x.y + x.z * x.z + x.w * x.w;
#pragma unroll
        for (int p = 0; p < PP; p++) {
            float4 u = reinterpret_cast<const float4*>(s_u + p * DD)[q];
            dot[p] += x.x * u.x + x.y * u.y + x.z * u.z + x.w * u.w;
        }
    }
#pragma unroll
    for (int off = 16; off; off >>= 1) {
        nrm2 += __shfl_xor_sync(0xffffffffu, nrm2, off);
#pragma unroll
        for (int p = 0; p < PP; p++) dot[p] += __shfl_xor_sync(0xffffffffu, dot[p], off);
    }
    if (lane < PP) {
        float dl = 0.f;
#pragma unroll
        for (int p = 0; p < PP; p++) if (lane == p) dl = dot[p];
        float denom = fmaxf(sqrtf(nrm2), EPSF);
        float v = dl / denom;
        float c = fmaxf(v, 0.f);
        float n = c / fmaxf(SQRT_S * c, EPSF);
        g_n[((size_t)lane * BB + b) * SS + s] = n;
    }
}

// ---------------- kernel 2: softmax over s (per p,b) -> weights ----------------
__global__ __launch_bounds__(256) void ksoft() {
    __shared__ float sn[SS];
    __shared__ float red[256];
    int pb = blockIdx.x;
    int t = threadIdx.x;
    const float* np = g_n + (size_t)pb * SS;
    float m = -1e30f;
    for (int i = t; i < SS; i += 256) { float v = np[i]; sn[i] = v; m = fmaxf(m, v); }
    red[t] = m; __syncthreads();
    for (int o = 128; o; o >>= 1) { if (t < o) red[t] = fmaxf(red[t], red[t + o]); __syncthreads(); }
    m = red[0]; __syncthreads();
    float sum = 0.f;
    for (int i = t; i < SS; i += 256) sum += expf(sn[i] - m);
    red[t] = sum; __syncthreads();
    for (int o = 128; o; o >>= 1) { if (t < o) red[t] += red[t + o]; __syncthreads(); }
    float inv = 1.0f / red[0];
    for (int i = t; i < SS; i += 256) g_wsm[(size_t)pb * SS + i] = expf(sn[i] - m) * inv;
}

// ---------------- kernel 3: a_v partials: sum_s w[p,b,s] * ctx[b,s,d] ----------------
// 512 threads cover all D as float2. 32 s-rows per block, 8-row load batches (MLP=8).
__global__ __launch_bounds__(512) void kavp(const float* __restrict__ ctx) {
    __shared__ float ws[32 * PP];
    int schunk = blockIdx.x, b = blockIdx.y;
    int t = threadIdx.x;
    if (t < 256) {
        int sl = t >> 3, p = t & 7;
        ws[t] = g_wsm[((size_t)p * BB + b) * SS + schunk * 32 + sl];
    }
    __syncthreads();
    float2 acc[PP];
#pragma unroll
    for (int p = 0; p < PP; p++) acc[p] = make_float2(0.f, 0.f);
    const float2* cp = reinterpret_cast<const float2*>(ctx) +
                       ((size_t)b * SS + schunk * 32) * 512 + t;
#pragma unroll
    for (int sl = 0; sl < 32; sl += 8) {
        float2 x[8];
#pragma unroll
        for (int r = 0; r < 8; r++) x[r] = cp[(size_t)(sl + r) * 512];
#pragma unroll
        for (int p = 0; p < PP; p++) {
#pragma unroll
            for (int r = 0; r < 8; r++) {
                float w = ws[(sl + r) * 8 + p];
                acc[p].x += w * x[r].x;
                acc[p].y += w * x[r].y;
            }
        }
    }
#pragma unroll
    for (int p = 0; p < PP; p++)
        reinterpret_cast<float2*>(g_avp)[(((size_t)schunk * PP + p) * BB + b) * 512 + t] = acc[p];
}

// ---------------- kernel 4: reduce partials ----------------
__global__ __launch_bounds__(256) void kavred() {
    int i = blockIdx.x * 256 + threadIdx.x;   // PP*BB*DD = 32768
    float s = 0.f;
#pragma unroll 8
    for (int c = 0; c < NSC; c++) s += g_avp[(size_t)c * PP * BB * DD + i];
    g_av[i] = s;
}

// ---------------- kernel 5: cos + double softmax -> gates ----------------
__global__ __launch_bounds__(1024) void kgate(const float* __restrict__ lora) {
    __shared__ float cs[PP * BB];
    int t = threadIdx.x, warp = t >> 5, lane = t & 31;
    int p = warp >> 2, b = warp & 3;
    float dot = 0.f, an2 = 0.f, en2 = 0.f;
    const float* e = lora + p * DD;
    const float* a = g_av + ((size_t)p * BB + b) * DD;
    for (int d = lane; d < DD; d += 32) {
        float ev = e[d], av = a[d];
        dot += ev * av; an2 += av * av; en2 += ev * ev;
    }
#pragma unroll
    for (int o = 16; o; o >>= 1) {
        dot += __shfl_xor_sync(0xffffffffu, dot, o);
        an2 += __shfl_xor_sync(0xffffffffu, an2, o);
        en2 += __shfl_xor_sync(0xffffffffu, en2, o);
    }
    if (lane == 0) cs[p * BB + b] = dot / fmaxf(sqrtf(en2) * sqrtf(an2), COSEPS);
    __syncthreads();
    if (t < BB) {
        int bb = t;
        float x[PP], m = -1e30f;
#pragma unroll
        for (int pp = 0; pp < PP; pp++) { x[pp] = cs[pp * BB + bb]; m = fmaxf(m, x[pp]); }
        float z = 0.f;
#pragma unroll
        for (int pp = 0; pp < PP; pp++) { x[pp] = expf(x[pp] - m); z += x[pp]; }
#pragma unroll
        for (int pp = 0; pp < PP; pp++) x[pp] /= z;      // s_t
        m = -1e30f;
#pragma unroll
        for (int pp = 0; pp < PP; pp++) m = fmaxf(m, x[pp]);
        z = 0.f;
#pragma unroll
        for (int pp = 0; pp < PP; pp++) { x[pp] = expf(x[pp] - m); z += x[pp]; }
#pragma unroll
        for (int pp = 0; pp < PP; pp++) g_gate[bb * PP + pp] = x[pp] / z;  // gate
    }
}

// ---------------- kernel 6a: Htab[p][v][h] = tanh(tables[p,v]@w1 + b1) ----------------
// Only P*V = 512 distinct token rows exist. Block = (p, 8 v's). 64 blocks.
__global__ __launch_bounds__(256) void khtab(const float* __restrict__ tables,
                                             const float* __restrict__ b1) {
    __shared__ float tok[8][DD];
    int p = blockIdx.x >> 3, vc = blockIdx.x & 7;
    int t = threadIdx.x, warp = t >> 5, lane = t & 31;
    const float* src = tables + ((size_t)p * VV + vc * 8) * DD;
    for (int i = t; i < 8 * DD; i += 256)
        tok[i >> 10][i & 1023] = src[i];
    __syncthreads();
#pragma unroll
    for (int j = 0; j < 6; j++) {
        int h = warp + j * 8;
        if (h < HH) {
            const float4* wrow = reinterpret_cast<const float4*>(g_w1t + (size_t)h * DD);
            float dot[8];
#pragma unroll
            for (int r = 0; r < 8; r++) dot[r] = 0.f;
#pragma unroll
            for (int it = 0; it < 8; it++) {
                float4 wv = wrow[lane + it * 32];
#pragma unroll
                for (int r = 0; r < 8; r++) {
                    float4 tv = reinterpret_cast<const float4*>(tok[r])[lane + it * 32];
                    dot[r] += wv.x * tv.x + wv.y * tv.y + wv.z * tv.z + wv.w * tv.w;
                }
            }
#pragma unroll
            for (int o = 16; o; o >>= 1)
#pragma unroll
                for (int r = 0; r < 8; r++) dot[r] += __shfl_xor_sync(0xffffffffu, dot[r], o);
            if (lane < 8) {
                float dl = 0.f;
#pragma unroll
                for (int r = 0; r < 8; r++) if (lane == r) dl = dot[r];
                g_htab[((size_t)p * VV + vc * 8 + lane) * HH + h] = tanhf(dl + b1[h]);
            }
        }
    }
}

// ---------------- kernel 6b: hbar[b,v,h] = sum_p gate[b,p] * Htab[p][prefix[b,v]][h] ----
__global__ __launch_bounds__(64) void khmix(const int* __restrict__ prefix) {
    int bv = blockIdx.x;
    int b = bv / VV;
    int t = threadIdx.x;
    if (t >= HH) return;
    int pf = prefix[bv];
    float s = 0.f;
#pragma unroll
    for (int p = 0; p < PP; p++)
        s += g_gate[b * PP + p] * g_htab[((size_t)p * VV + pf) * HH + t];
    g_hbar[(size_t)bv * HH + t] = s;
}

// ---------------- kernel 7: out = hbar @ w2 + b2 (packed f32x2 FFMA2) ----------------
__device__ __forceinline__ unsigned long long fma2(unsigned long long a,
                                                   unsigned long long b,
                                                   unsigned long long c) {
    unsigned long long d;
    asm("fma.rn.f32x2 %0, %1, %2, %3;" : "=l"(d) : "l"(a), "l"(b), "l"(c));
    return d;
}

// 32 rows per block (blockIdx.y), 256 k per block (blockIdx.x). 128 threads.
__global__ __launch_bounds__(128) void kout(const float* __restrict__ w2,
                                            const float* __restrict__ b2,
                                            float* __restrict__ out) {
    __shared__ unsigned long long hb2[32 * HH];   // hbar duplicated {v,v}
    int r0 = blockIdx.y * 32;
    int t = threadIdx.x;
    for (int i = t; i < 32 * HH; i += 128) {
        float v = g_hbar[(size_t)(r0 + i / HH) * HH + (i % HH)];
        float2 d2 = make_float2(v, v);
        hb2[i] = *reinterpret_cast<unsigned long long*>(&d2);
    }
    __syncthreads();
    int kp = blockIdx.x * 256 + t * 2;
    unsigned long long wcol[HH];
#pragma unroll
    for (int h = 0; h < HH; h++) {
        float2 wv = *reinterpret_cast<const float2*>(w2 + (size_t)h * KK + kp);
        wcol[h] = *reinterpret_cast<unsigned long long*>(&wv);
    }
    float2 bv = *reinterpret_cast<const float2*>(b2 + kp);
    unsigned long long binit = *reinterpret_cast<unsigned long long*>(&bv);
    for (int rg = 0; rg < 32; rg += 4) {
        unsigned long long a0 = binit, a1 = binit, a2 = binit, a3 = binit;
#pragma unroll
        for (int h = 0; h < HH; h++) {
            a0 = fma2(wcol[h], hb2[(rg + 0) * HH + h], a0);
            a1 = fma2(wcol[h], hb2[(rg + 1) * HH + h], a1);
            a2 = fma2(wcol[h], hb2[(rg + 2) * HH + h], a2);
            a3 = fma2(wcol[h], hb2[(rg + 3) * HH + h], a3);
        }
        *reinterpret_cast<float2*>(out + (size_t)(r0 + rg + 0) * KK + kp) = *reinterpret_cast<float2*>(&a0);
        *reinterpret_cast<float2*>(out + (size_t)(r0 + rg + 1) * KK + kp) = *reinterpret_cast<float2*>(&a1);
        *reinterpret_cast<float2*>(out + (size_t)(r0 + rg + 2) * KK + kp) = *reinterpret_cast<float2*>(&a2);
        *reinterpret_cast<float2*>(out + (size_t)(r0 + rg + 3) * KK + kp) = *reinterpret_cast<float2*>(&a3);
    }
}

// ---------------- launcher ----------------
extern "C" void kernel_launch(void* const* d_in, const int* in_sizes, int n_in,
                              void* d_out, int out_size) {
    const int* prefix = nullptr;
    const float *ctx = nullptr, *tables = nullptr, *lora = nullptr;
    const float *w1 = nullptr, *b1 = nullptr, *w2 = nullptr, *b2 = nullptr;
    for (int i = 0; i < n_in; i++) {
        switch (in_sizes[i]) {
            case 256:     prefix = (const int*)d_in[i];   break;  // (B,V) int32
            case 8388608: ctx    = (const float*)d_in[i]; break;  // (B,S,D)
            case 524288:  tables = (const float*)d_in[i]; break;  // (P,V,D)
            case 8192:    lora   = (const float*)d_in[i]; break;  // (P,D)
            case 43008:   w1     = (const float*)d_in[i]; break;  // (D,H)
            case 42:      b1     = (const float*)d_in[i]; break;  // (H,)
            case 2064384: w2     = (const float*)d_in[i]; break;  // (H,K)
            case 49152:   b2     = (const float*)d_in[i]; break;  // (K,)
        }
    }
    float* out = (float*)d_out;

    kprep<<<168, 256>>>(lora, w1);
    knorm<<<1024, 256>>>(ctx);
    ksoft<<<32, 256>>>();
    kavp<<<dim3(NSC, 4), 512>>>(ctx);
    kavred<<<128, 256>>>();
    kgate<<<1, 1024>>>(lora);
    khtab<<<64, 256>>>(tables, b1);
    khmix<<<256, 64>>>(prefix);
    kout<<<dim3(KK / 256, 8), 128>>>(w2, b2, out);
}

// round 4
// speedup vs baseline: 1.1720x; 1.1720x over previous
#include <cuda_runtime.h>
#include <math.h>

#define BB 4
#define SS 2048
#define VV 64
#define DD 1024
#define PP 8
#define HH 42
#define KK 49152
#define EPSF 1e-12f
#define COSEPS 1e-8f
#define SQRT_S 45.254834f   // sqrt(2048)
#define NSC 64              // s-chunks in kavp (32 s each)
#define W1PAD 1028          // padded row stride for w1 in smem (floats)

// ---------------- scratch (static device globals; no allocs allowed) ----------------
__device__ float g_n[PP * BB * SS];         // n values
__device__ float g_wsm[PP * BB * SS];       // softmax weights over s
__device__ float g_avp[NSC * PP * BB * DD]; // a_v partials per s-chunk (8MB)
__device__ float g_av[PP * BB * DD];        // a_v
__device__ float g_cos[PP * BB];            // cosine sims
__device__ float g_htab[PP * VV * HH];      // tanh(tables@w1+b1) table [512][42]
__device__ float g_hbar[BB * VV * HH];      // gate-combined hidden

// ---------------- kernel 1: per-(b,s) row norm + 8 dots -> n[p,b,s] ----------------
__global__ __launch_bounds__(256) void knorm(const float* __restrict__ ctx,
                                             const float* __restrict__ lora) {
    __shared__ float s_u[PP * DD];
    for (int i = threadIdx.x; i < PP * DD; i += 256) {
        float e = lora[i];
        s_u[i] = e / fmaxf(2.0f * fabsf(e), EPSF);
    }
    __syncthreads();
    int warp = threadIdx.x >> 5, lane = threadIdx.x & 31;
    int row = blockIdx.x * 8 + warp;          // [0, B*S)
    int b = row / SS, s = row % SS;
    const float4* x4 = reinterpret_cast<const float4*>(ctx + (size_t)row * DD);
    float nrm2 = 0.f;
    float dot[PP];
#pragma unroll
    for (int p = 0; p < PP; p++) dot[p] = 0.f;
#pragma unroll
    for (int it = 0; it < 8; it++) {
        int q = lane + it * 32;               // float4 index 0..255
        float4 x = x4[q];
        nrm2 += x.x * x.x + x.y * x.y + x.z * x.z + x.w * x.w;
#pragma unroll
        for (int p = 0; p < PP; p++) {
            float4 u = reinterpret_cast<const float4*>(s_u + p * DD)[q];
            dot[p] += x.x * u.x + x.y * u.y + x.z * u.z + x.w * u.w;
        }
    }
#pragma unroll
    for (int off = 16; off; off >>= 1) {
        nrm2 += __shfl_xor_sync(0xffffffffu, nrm2, off);
#pragma unroll
        for (int p = 0; p < PP; p++) dot[p] += __shfl_xor_sync(0xffffffffu, dot[p], off);
    }
    if (lane < PP) {
        float dl = 0.f;
#pragma unroll
        for (int p = 0; p < PP; p++) if (lane == p) dl = dot[p];
        float denom = fmaxf(sqrtf(nrm2), EPSF);
        float v = dl / denom;
        float c = fmaxf(v, 0.f);
        float n = c / fmaxf(SQRT_S * c, EPSF);
        g_n[((size_t)lane * BB + b) * SS + s] = n;
    }
}

// ---------------- kernel 2: softmax over s (per p,b) -> weights ----------------
__global__ __launch_bounds__(256) void ksoft() {
    __shared__ float sn[SS];
    __shared__ float red[256];
    int pb = blockIdx.x;
    int t = threadIdx.x;
    const float* np = g_n + (size_t)pb * SS;
    float m = -1e30f;
    for (int i = t; i < SS; i += 256) { float v = np[i]; sn[i] = v; m = fmaxf(m, v); }
    red[t] = m; __syncthreads();
    for (int o = 128; o; o >>= 1) { if (t < o) red[t] = fmaxf(red[t], red[t + o]); __syncthreads(); }
    m = red[0]; __syncthreads();
    float sum = 0.f;
    for (int i = t; i < SS; i += 256) sum += expf(sn[i] - m);
    red[t] = sum; __syncthreads();
    for (int o = 128; o; o >>= 1) { if (t < o) red[t] += red[t + o]; __syncthreads(); }
    float inv = 1.0f / red[0];
    for (int i = t; i < SS; i += 256) g_wsm[(size_t)pb * SS + i] = expf(sn[i] - m) * inv;
}

// ---------------- kernel 3: a_v partials: sum_s w[p,b,s] * ctx[b,s,d] ----------------
// grid (NSC, B, 2): 32 s-rows, half of D (512 floats) per block. 256 thr, float2/thread.
__global__ __launch_bounds__(256) void kavp(const float* __restrict__ ctx) {
    __shared__ float ws[32 * PP];
    int schunk = blockIdx.x, b = blockIdx.y, dh = blockIdx.z;
    int t = threadIdx.x;
    if (t < 256) {
        int sl = t >> 3, p = t & 7;
        ws[t] = g_wsm[((size_t)p * BB + b) * SS + schunk * 32 + sl];
    }
    __syncthreads();
    float2 acc[PP];
#pragma unroll
    for (int p = 0; p < PP; p++) acc[p] = make_float2(0.f, 0.f);
    const float2* cp = reinterpret_cast<const float2*>(ctx) +
                       ((size_t)b * SS + schunk * 32) * 512 + dh * 256 + t;
#pragma unroll
    for (int sl = 0; sl < 32; sl += 8) {
        float2 x[8];
#pragma unroll
        for (int r = 0; r < 8; r++) x[r] = cp[(size_t)(sl + r) * 512];
#pragma unroll
        for (int p = 0; p < PP; p++) {
#pragma unroll
            for (int r = 0; r < 8; r++) {
                float w = ws[(sl + r) * 8 + p];
                acc[p].x += w * x[r].x;
                acc[p].y += w * x[r].y;
            }
        }
    }
#pragma unroll
    for (int p = 0; p < PP; p++)
        reinterpret_cast<float2*>(g_avp)[(((size_t)schunk * PP + p) * BB + b) * 512 + dh * 256 + t] = acc[p];
}

// ---------------- kernel 4: reduce partials ----------------
__global__ __launch_bounds__(256) void kavred() {
    int i = blockIdx.x * 256 + threadIdx.x;   // PP*BB*DD = 32768
    float s = 0.f;
#pragma unroll 8
    for (int c = 0; c < NSC; c++) s += g_avp[(size_t)c * PP * BB * DD + i];
    g_av[i] = s;
}

// ---------------- kernel 5: cos per (p,b) -> g_cos (32 parallel blocks) ----------------
__global__ __launch_bounds__(256) void kgate32(const float* __restrict__ lora) {
    int p = blockIdx.x >> 2, b = blockIdx.x & 3;
    int t = threadIdx.x, warp = t >> 5, lane = t & 31;
    float dot = 0.f, an2 = 0.f, en2 = 0.f;
    const float* e = lora + p * DD;
    const float* a = g_av + ((size_t)p * BB + b) * DD;
    for (int d = t; d < DD; d += 256) {
        float ev = e[d], av = a[d];
        dot += ev * av; an2 += av * av; en2 += ev * ev;
    }
#pragma unroll
    for (int o = 16; o; o >>= 1) {
        dot += __shfl_xor_sync(0xffffffffu, dot, o);
        an2 += __shfl_xor_sync(0xffffffffu, an2, o);
        en2 += __shfl_xor_sync(0xffffffffu, en2, o);
    }
    __shared__ float r1[8], r2[8], r3[8];
    if (lane == 0) { r1[warp] = dot; r2[warp] = an2; r3[warp] = en2; }
    __syncthreads();
    if (t == 0) {
        float d0 = 0.f, a0 = 0.f, e0 = 0.f;
#pragma unroll
        for (int w = 0; w < 8; w++) { d0 += r1[w]; a0 += r2[w]; e0 += r3[w]; }
        g_cos[p * BB + b] = d0 / fmaxf(sqrtf(e0) * sqrtf(a0), COSEPS);
    }
}

// ---------------- kernel 6a: Htab[p][v][h] = tanh(tables[p,v]@w1 + b1) ----------------
// w1 staged transposed (padded) + 8 tok rows in dynamic smem; all inner ops are LDS.
__global__ __launch_bounds__(256) void khtab(const float* __restrict__ tables,
                                             const float* __restrict__ w1,
                                             const float* __restrict__ b1) {
    extern __shared__ float dsm[];
    float* w1s = dsm;                 // [HH][W1PAD]
    float* tok = dsm + HH * W1PAD;    // [8][DD]
    int p = blockIdx.x >> 3, vc = blockIdx.x & 7;
    int t = threadIdx.x, warp = t >> 5, lane = t & 31;
    for (int i = t; i < DD * HH; i += 256) {
        int d = i / HH, h = i - d * HH;
        w1s[h * W1PAD + d] = w1[i];
    }
    const float* src = tables + ((size_t)p * VV + vc * 8) * DD;
    for (int i = t; i < 8 * DD; i += 256)
        tok[(i >> 10) * DD + (i & 1023)] = src[i];
    __syncthreads();
#pragma unroll
    for (int j = 0; j < 6; j++) {
        int h = warp + j * 8;
        if (h < HH) {
            const float4* wrow = reinterpret_cast<const float4*>(w1s + (size_t)h * W1PAD);
            float dot[8];
#pragma unroll
            for (int r = 0; r < 8; r++) dot[r] = 0.f;
#pragma unroll
            for (int it = 0; it < 8; it++) {
                float4 wv = wrow[lane + it * 32];
#pragma unroll
                for (int r = 0; r < 8; r++) {
                    float4 tv = reinterpret_cast<const float4*>(tok + r * DD)[lane + it * 32];
                    dot[r] += wv.x * tv.x + wv.y * tv.y + wv.z * tv.z + wv.w * tv.w;
                }
            }
#pragma unroll
            for (int o = 16; o; o >>= 1)
#pragma unroll
                for (int r = 0; r < 8; r++) dot[r] += __shfl_xor_sync(0xffffffffu, dot[r], o);
            if (lane < 8) {
                float dl = 0.f;
#pragma unroll
                for (int r = 0; r < 8; r++) if (lane == r) dl = dot[r];
                g_htab[((size_t)p * VV + vc * 8 + lane) * HH + h] = tanhf(dl + b1[h]);
            }
        }
    }
}

// ---- kernel 6b: gates from cos (redundant per block) + hbar gather ----
__global__ __launch_bounds__(64) void khmix(const int* __restrict__ prefix) {
    int bv = blockIdx.x;
    int b = bv / VV;
    int t = threadIdx.x;
    // every thread computes the 8 gates for its b (double softmax over p)
    float x[PP], m = -1e30f;
#pragma unroll
    for (int p = 0; p < PP; p++) { x[p] = g_cos[p * BB + b]; m = fmaxf(m, x[p]); }
    float z = 0.f;
#pragma unroll
    for (int p = 0; p < PP; p++) { x[p] = expf(x[p] - m); z += x[p]; }
#pragma unroll
    for (int p = 0; p < PP; p++) x[p] /= z;          // s_t
    m = -1e30f;
#pragma unroll
    for (int p = 0; p < PP; p++) m = fmaxf(m, x[p]);
    z = 0.f;
#pragma unroll
    for (int p = 0; p < PP; p++) { x[p] = expf(x[p] - m); z += x[p]; }
#pragma unroll
    for (int p = 0; p < PP; p++) x[p] /= z;          // gate
    if (t < HH) {
        int pf = prefix[bv];
        float s = 0.f;
#pragma unroll
        for (int p = 0; p < PP; p++)
            s += x[p] * g_htab[((size_t)p * VV + pf) * HH + t];
        g_hbar[(size_t)bv * HH + t] = s;
    }
}

// ---------------- kernel 7: out = hbar @ w2 + b2 (packed f32x2 FFMA2) ----------------
__device__ __forceinline__ unsigned long long fma2(unsigned long long a,
                                                   unsigned long long b,
                                                   unsigned long long c) {
    unsigned long long d;
    asm("fma.rn.f32x2 %0, %1, %2, %3;" : "=l"(d) : "l"(a), "l"(b), "l"(c));
    return d;
}

// 32 rows per block (blockIdx.y), 256 k per block (blockIdx.x). 128 threads.
__global__ __launch_bounds__(128) void kout(const float* __restrict__ w2,
                                            const float* __restrict__ b2,
                                            float* __restrict__ out) {
    __shared__ unsigned long long hb2[32 * HH];   // hbar duplicated {v,v}
    int r0 = blockIdx.y * 32;
    int t = threadIdx.x;
    for (int i = t; i < 32 * HH; i += 128) {
        float v = g_hbar[(size_t)(r0 + i / HH) * HH + (i % HH)];
        float2 d2 = make_float2(v, v);
        hb2[i] = *reinterpret_cast<unsigned long long*>(&d2);
    }
    __syncthreads();
    int kp = blockIdx.x * 256 + t * 2;
    unsigned long long wcol[HH];
#pragma unroll
    for (int h = 0; h < HH; h++) {
        float2 wv = *reinterpret_cast<const float2*>(w2 + (size_t)h * KK + kp);
        wcol[h] = *reinterpret_cast<unsigned long long*>(&wv);
    }
    float2 bv = *reinterpret_cast<const float2*>(b2 + kp);
    unsigned long long binit = *reinterpret_cast<unsigned long long*>(&bv);
    for (int rg = 0; rg < 32; rg += 4) {
        unsigned long long a0 = binit, a1 = binit, a2 = binit, a3 = binit;
#pragma unroll
        for (int h = 0; h < HH; h++) {
            a0 = fma2(wcol[h], hb2[(rg + 0) * HH + h], a0);
            a1 = fma2(wcol[h], hb2[(rg + 1) * HH + h], a1);
            a2 = fma2(wcol[h], hb2[(rg + 2) * HH + h], a2);
            a3 = fma2(wcol[h], hb2[(rg + 3) * HH + h], a3);
        }
        *reinterpret_cast<float2*>(out + (size_t)(r0 + rg + 0) * KK + kp) = *reinterpret_cast<float2*>(&a0);
        *reinterpret_cast<float2*>(out + (size_t)(r0 + rg + 1) * KK + kp) = *reinterpret_cast<float2*>(&a1);
        *reinterpret_cast<float2*>(out + (size_t)(r0 + rg + 2) * KK + kp) = *reinterpret_cast<float2*>(&a2);
        *reinterpret_cast<float2*>(out + (size_t)(r0 + rg + 3) * KK + kp) = *reinterpret_cast<float2*>(&a3);
    }
}

// ---------------- launcher ----------------
extern "C" void kernel_launch(void* const* d_in, const int* in_sizes, int n_in,
                              void* d_out, int out_size) {
    const int* prefix = nullptr;
    const float *ctx = nullptr, *tables = nullptr, *lora = nullptr;
    const float *w1 = nullptr, *b1 = nullptr, *w2 = nullptr, *b2 = nullptr;
    for (int i = 0; i < n_in; i++) {
        switch (in_sizes[i]) {
            case 256:     prefix = (const int*)d_in[i];   break;  // (B,V) int32
            case 8388608: ctx    = (const float*)d_in[i]; break;  // (B,S,D)
            case 524288:  tables = (const float*)d_in[i]; break;  // (P,V,D)
            case 8192:    lora   = (const float*)d_in[i]; break;  // (P,D)
            case 43008:   w1     = (const float*)d_in[i]; break;  // (D,H)
            case 42:      b1     = (const float*)d_in[i]; break;  // (H,)
            case 2064384: w2     = (const float*)d_in[i]; break;  // (H,K)
            case 49152:   b2     = (const float*)d_in[i]; break;  // (K,)
        }
    }
    float* out = (float*)d_out;

    const int khtab_smem = (HH * W1PAD + 8 * DD) * 4;   // 205,472 B
    cudaFuncSetAttribute(khtab, cudaFuncAttributeMaxDynamicSharedMemorySize, khtab_smem);

    khtab<<<64, 256, khtab_smem>>>(tables, w1, b1);
    knorm<<<1024, 256>>>(ctx, lora);
    ksoft<<<32, 256>>>();
    kavp<<<dim3(NSC, 4, 2), 256>>>(ctx);
    kavred<<<128, 256>>>();
    kgate32<<<32, 256>>>(lora);
    khmix<<<256, 64>>>(prefix);
    kout<<<dim3(KK / 256, 8), 128>>>(w2, b2, out);
}

// round 5
// speedup vs baseline: 1.2224x; 1.0430x over previous
#include <cuda_runtime.h>
#include <math.h>

#define BB 4
#define SS 2048
#define VV 64
#define DD 1024
#define PP 8
#define HH 42
#define KK 49152
#define EPSF 1e-12f
#define COSEPS 1e-8f
#define SQRT_S 45.254834f   // sqrt(2048)
#define NSC 64              // s-chunks in kavp (32 s each)
#define GRID 296            // 2 blocks/SM x 148 SMs — all co-resident
#define THR 256

// ---------------- scratch (static device globals; no allocs allowed) ----------------
__device__ float g_w1t[HH * DD];              // w1 transposed [H][D]
__device__ float g_n[PP * BB * SS];           // n values
__device__ float g_wsm[PP * BB * SS];         // softmax weights over s
__device__ float g_avp[PP * BB * NSC * DD];   // a_v partials, [pb][chunk][d] (8MB)
__device__ float g_cos[PP * BB];              // cosine sims
__device__ float g_htab[PP * VV * HH];        // tanh(tables@w1+b1) [512][42]
__device__ unsigned g_cnt[4];                 // barrier counters (self-resetting)
__device__ unsigned g_flag[4];                // barrier sense flags (toggle, replay-safe)

// ---------------- shared memory union (max 32KB -> 2 blocks/SM fits) ----------------
union SMem {
    struct { float u[PP * DD]; } norm;                       // 32768 B
    struct { float sn[SS]; float red[256]; } soft;           // 9216 B
    struct { float ws[32 * PP]; } avp;                       // 1024 B
    struct { float red3[24]; } cosr;                         // 96 B
    struct { float tok[2 * DD]; } htab;                      // 8192 B
    struct { float sgate[32]; unsigned long long hb2[32 * HH]; } outp; // 10880 B
};

// ---------------- device-wide sense-reversing barrier ----------------
__device__ __forceinline__ void gsync(int ph) {
    __syncthreads();
    if (threadIdx.x == 0) {
        volatile unsigned* fl = &g_flag[ph];
        unsigned s0 = *fl;                    // read sense BEFORE arriving
        __threadfence();
        unsigned old = atomicAdd(&g_cnt[ph], 1u);
        if (old == GRID - 1) {
            g_cnt[ph] = 0;                    // safe: nobody reads cnt while spinning
            __threadfence();
            *fl = s0 ^ 1u;                    // release
        } else {
            while (*fl == s0) { }             // spin on flag
        }
    }
    __syncthreads();
}

__device__ __forceinline__ unsigned long long fma2(unsigned long long a,
                                                   unsigned long long b,
                                                   unsigned long long c) {
    unsigned long long d;
    asm("fma.rn.f32x2 %0, %1, %2, %3;" : "=l"(d) : "l"(a), "l"(b), "l"(c));
    return d;
}

__global__ __launch_bounds__(THR, 2) void mega(
    const int* __restrict__ prefix, const float* __restrict__ ctx,
    const float* __restrict__ tables, const float* __restrict__ lora,
    const float* __restrict__ w1, const float* __restrict__ b1,
    const float* __restrict__ w2, const float* __restrict__ b2,
    float* __restrict__ out)
{
    __shared__ SMem sm;
    const int t = threadIdx.x, warp = t >> 5, lane = t & 31;
    const int blk = blockIdx.x;

    // ================= P1: knorm — n[p,b,s] =================
    {
        float* su = sm.norm.u;
        for (int i = t; i < PP * DD; i += THR) {
            float e = lora[i];
            su[i] = e / fmaxf(2.0f * fabsf(e), EPSF);
        }
        __syncthreads();
        for (int row = blk * 8 + warp; row < BB * SS; row += GRID * 8) {
            int b = row >> 11, s = row & 2047;
            const float4* x4 = reinterpret_cast<const float4*>(ctx + (size_t)row * DD);
            float nrm2 = 0.f;
            float dot[PP];
#pragma unroll
            for (int p = 0; p < PP; p++) dot[p] = 0.f;
#pragma unroll
            for (int it = 0; it < 8; it++) {
                int q = lane + it * 32;
                float4 x = x4[q];
                nrm2 += x.x * x.x + x.y * x.y + x.z * x.z + x.w * x.w;
#pragma unroll
                for (int p = 0; p < PP; p++) {
                    float4 u = reinterpret_cast<const float4*>(su + p * DD)[q];
                    dot[p] += x.x * u.x + x.y * u.y + x.z * u.z + x.w * u.w;
                }
            }
#pragma unroll
            for (int o = 16; o; o >>= 1) {
                nrm2 += __shfl_xor_sync(0xffffffffu, nrm2, o);
#pragma unroll
                for (int p = 0; p < PP; p++) dot[p] += __shfl_xor_sync(0xffffffffu, dot[p], o);
            }
            if (lane < PP) {
                float dl = 0.f;
#pragma unroll
                for (int p = 0; p < PP; p++) if (lane == p) dl = dot[p];
                float v = dl / fmaxf(sqrtf(nrm2), EPSF);
                float c = fmaxf(v, 0.f);
                g_n[((size_t)lane * BB + b) * SS + s] = c / fmaxf(SQRT_S * c, EPSF);
            }
        }
    }
    gsync(0);

    // ================= P2: ksoft (blk<32)  ||  w1 transpose (blk>=32) =================
    if (blk < 32) {
        int pb = blk;
        float* sn = sm.soft.sn;
        float* red = sm.soft.red;
        const float* np = g_n + (size_t)pb * SS;
        float m = -1e30f;
        for (int i = t; i < SS; i += THR) { float v = np[i]; sn[i] = v; m = fmaxf(m, v); }
        red[t] = m; __syncthreads();
        for (int o = 128; o; o >>= 1) { if (t < o) red[t] = fmaxf(red[t], red[t + o]); __syncthreads(); }
        m = red[0]; __syncthreads();
        float sum = 0.f;
        for (int i = t; i < SS; i += THR) sum += expf(sn[i] - m);
        red[t] = sum; __syncthreads();
        for (int o = 128; o; o >>= 1) { if (t < o) red[t] += red[t + o]; __syncthreads(); }
        float inv = 1.0f / red[0];
        for (int i = t; i < SS; i += THR) g_wsm[(size_t)pb * SS + i] = expf(sn[i] - m) * inv;
    } else {
        int idx = (blk - 32) * THR + t;
        if (idx < DD * HH) {
            int d = idx / HH, h = idx - d * HH;
            g_w1t[(size_t)h * DD + d] = w1[idx];
        }
    }
    gsync(1);

    // ================= P3: kavp — a_v partials =================
    for (int tile = blk; tile < 512; tile += GRID) {
        int schunk = tile & 63, rem = tile >> 6;
        int b = rem & 3, dh = rem >> 2;
        __syncthreads();
        sm.avp.ws[t & 255] = g_wsm[((size_t)(t & 7) * BB + b) * SS + schunk * 32 + (t >> 3)];
        __syncthreads();
        float2 acc[PP];
#pragma unroll
        for (int p = 0; p < PP; p++) acc[p] = make_float2(0.f, 0.f);
        const float2* cp = reinterpret_cast<const float2*>(ctx) +
                           ((size_t)b * SS + schunk * 32) * 512 + dh * 256 + t;
        const float* ws = sm.avp.ws;
#pragma unroll
        for (int sl = 0; sl < 32; sl += 8) {
            float2 x[8];
#pragma unroll
            for (int r = 0; r < 8; r++) x[r] = cp[(size_t)(sl + r) * 512];
#pragma unroll
            for (int p = 0; p < PP; p++) {
#pragma unroll
                for (int r = 0; r < 8; r++) {
                    float w = ws[(sl + r) * 8 + p];
                    acc[p].x += w * x[r].x;
                    acc[p].y += w * x[r].y;
                }
            }
        }
#pragma unroll
        for (int p = 0; p < PP; p++)
            reinterpret_cast<float2*>(g_avp)[((size_t)(p * BB + b) * NSC + schunk) * 512 + dh * 256 + t] = acc[p];
    }
    gsync(2);

    // ================= P4: avred+cos (blk<32)  ||  htab (32<=blk<288) =================
    if (blk < 32) {
        int pb = blk, p = pb >> 2;
        float dot = 0.f, an2 = 0.f, en2 = 0.f;
        for (int d = t; d < DD; d += THR) {
            float s = 0.f;
#pragma unroll 8
            for (int c = 0; c < NSC; c++) s += g_avp[((size_t)pb * NSC + c) * DD + d];
            float e = lora[p * DD + d];
            dot += e * s; an2 += s * s; en2 += e * e;
        }
#pragma unroll
        for (int o = 16; o; o >>= 1) {
            dot += __shfl_xor_sync(0xffffffffu, dot, o);
            an2 += __shfl_xor_sync(0xffffffffu, an2, o);
            en2 += __shfl_xor_sync(0xffffffffu, en2, o);
        }
        if (lane == 0) { sm.cosr.red3[warp] = dot; sm.cosr.red3[8 + warp] = an2; sm.cosr.red3[16 + warp] = en2; }
        __syncthreads();
        if (t == 0) {
            float D = 0.f, A = 0.f, E = 0.f;
#pragma unroll
            for (int w = 0; w < 8; w++) { D += sm.cosr.red3[w]; A += sm.cosr.red3[8 + w]; E += sm.cosr.red3[16 + w]; }
            g_cos[pb] = D / fmaxf(sqrtf(E) * sqrtf(A), COSEPS);
        }
    } else if (blk < 288) {
        int pair = blk - 32;                       // rows 2*pair, 2*pair+1 of [512][D]
        float* tok = sm.htab.tok;
        const float* src = tables + (size_t)pair * 2 * DD;
        for (int i = t; i < 2 * DD; i += THR) tok[i] = src[i];
        __syncthreads();
#pragma unroll
        for (int j = 0; j < 6; j++) {
            int h = warp + j * 8;
            if (h < HH) {
                const float4* wr = reinterpret_cast<const float4*>(g_w1t + (size_t)h * DD);
                float d0 = 0.f, d1 = 0.f;
#pragma unroll
                for (int it = 0; it < 8; it++) {
                    int q = lane + it * 32;
                    float4 wv = wr[q];
                    float4 t0 = reinterpret_cast<const float4*>(tok)[q];
                    float4 t1 = reinterpret_cast<const float4*>(tok + DD)[q];
                    d0 += wv.x * t0.x + wv.y * t0.y + wv.z * t0.z + wv.w * t0.w;
                    d1 += wv.x * t1.x + wv.y * t1.y + wv.z * t1.z + wv.w * t1.w;
                }
#pragma unroll
                for (int o = 16; o; o >>= 1) {
                    d0 += __shfl_xor_sync(0xffffffffu, d0, o);
                    d1 += __shfl_xor_sync(0xffffffffu, d1, o);
                }
                if (lane == 0) {
                    float bh = b1[h];
                    g_htab[(size_t)(pair * 2 + 0) * HH + h] = tanhf(d0 + bh);
                    g_htab[(size_t)(pair * 2 + 1) * HH + h] = tanhf(d1 + bh);
                }
            }
        }
    }
    gsync(3);

    // ================= P5: kout — gates + hbar inline, then hbar @ w2 + b2 =================
    for (int tile = blk; tile < 768; tile += GRID) {
        int kslab = tile % 96, rslab = tile / 96;
        int r0 = rslab * 32;
        __syncthreads();                           // protect smem from prev iteration
        if (t < 32) {
            // double softmax over p for batch bq = t>>3; store gate for p = t&7
            int bq = t >> 3, p = t & 7;
            float x[PP], m = -1e30f;
#pragma unroll
            for (int pp = 0; pp < PP; pp++) { x[pp] = g_cos[pp * BB + bq]; m = fmaxf(m, x[pp]); }
            float z = 0.f;
#pragma unroll
            for (int pp = 0; pp < PP; pp++) { x[pp] = expf(x[pp] - m); z += x[pp]; }
#pragma unroll
            for (int pp = 0; pp < PP; pp++) x[pp] /= z;        // s_t
            m = -1e30f;
#pragma unroll
            for (int pp = 0; pp < PP; pp++) m = fmaxf(m, x[pp]);
            z = 0.f;
#pragma unroll
            for (int pp = 0; pp < PP; pp++) { x[pp] = expf(x[pp] - m); z += x[pp]; }
            sm.outp.sgate[t] = x[p] / z;                        // gate[bq][p]
        }
        __syncthreads();
        for (int i = t; i < 32 * HH; i += THR) {
            int r = i / HH, h = i - r * HH;
            int bv = r0 + r;
            int pf = prefix[bv];
            int bq = bv >> 6;
            float s = 0.f;
#pragma unroll
            for (int p = 0; p < PP; p++)
                s += sm.outp.sgate[bq * 8 + p] * g_htab[((size_t)p * VV + pf) * HH + h];
            float2 d2 = make_float2(s, s);
            sm.outp.hb2[i] = *reinterpret_cast<unsigned long long*>(&d2);
        }
        __syncthreads();
        int kp = kslab * 512 + t * 2;
        unsigned long long wcol[HH];
#pragma unroll
        for (int h = 0; h < HH; h++) {
            float2 wv = *reinterpret_cast<const float2*>(w2 + (size_t)h * KK + kp);
            wcol[h] = *reinterpret_cast<unsigned long long*>(&wv);
        }
        float2 bv2 = *reinterpret_cast<const float2*>(b2 + kp);
        unsigned long long binit = *reinterpret_cast<unsigned long long*>(&bv2);
        const unsigned long long* hb2 = sm.outp.hb2;
        for (int rg = 0; rg < 32; rg += 4) {
            unsigned long long a0 = binit, a1 = binit, a2 = binit, a3 = binit;
#pragma unroll
            for (int h = 0; h < HH; h++) {
                a0 = fma2(wcol[h], hb2[(rg + 0) * HH + h], a0);
                a1 = fma2(wcol[h], hb2[(rg + 1) * HH + h], a1);
                a2 = fma2(wcol[h], hb2[(rg + 2) * HH + h], a2);
                a3 = fma2(wcol[h], hb2[(rg + 3) * HH + h], a3);
            }
            *reinterpret_cast<float2*>(out + (size_t)(r0 + rg + 0) * KK + kp) = *reinterpret_cast<float2*>(&a0);
            *reinterpret_cast<float2*>(out + (size_t)(r0 + rg + 1) * KK + kp) = *reinterpret_cast<float2*>(&a1);
            *reinterpret_cast<float2*>(out + (size_t)(r0 + rg + 2) * KK + kp) = *reinterpret_cast<float2*>(&a2);
            *reinterpret_cast<float2*>(out + (size_t)(r0 + rg + 3) * KK + kp) = *reinterpret_cast<float2*>(&a3);
        }
    }
}

// ---------------- launcher ----------------
extern "C" void kernel_launch(void* const* d_in, const int* in_sizes, int n_in,
                              void* d_out, int out_size) {
    const int* prefix = nullptr;
    const float *ctx = nullptr, *tables = nullptr, *lora = nullptr;
    const float *w1 = nullptr, *b1 = nullptr, *w2 = nullptr, *b2 = nullptr;
    for (int i = 0; i < n_in; i++) {
        switch (in_sizes[i]) {
            case 256:     prefix = (const int*)d_in[i];   break;  // (B,V) int32
            case 8388608: ctx    = (const float*)d_in[i]; break;  // (B,S,D)
            case 524288:  tables = (const float*)d_in[i]; break;  // (P,V,D)
            case 8192:    lora   = (const float*)d_in[i]; break;  // (P,D)
            case 43008:   w1     = (const float*)d_in[i]; break;  // (D,H)
            case 42:      b1     = (const float*)d_in[i]; break;  // (H,)
            case 2064384: w2     = (const float*)d_in[i]; break;  // (H,K)
            case 49152:   b2     = (const float*)d_in[i]; break;  // (K,)
        }
    }
    float* out = (float*)d_out;
    mega<<<GRID, THR>>>(prefix, ctx, tables, lora, w1, b1, w2, b2, out);
}

// round 6
// speedup vs baseline: 1.4296x; 1.1695x over previous
#include <cuda_runtime.h>
#include <math.h>

#define BB 4
#define SS 2048
#define VV 64
#define DD 1024
#define PP 8
#define HH 42
#define KK 49152
#define EPSF 1e-12f
#define COSEPS 1e-8f
#define SQRT_S 45.254834f   // sqrt(2048)
#define NSC 64              // s-chunks in kavp (32 s each)

// ---------------- scratch (static device globals; no allocs allowed) ----------------
__device__ float g_w1t[HH * DD];              // w1 transposed [H][D]
__device__ float g_n[PP * BB * SS];           // n values
__device__ float g_wsm[PP * BB * SS];         // softmax weights over s
__device__ float g_avp[PP * BB * NSC * DD];   // a_v partials, [pb][chunk][d] (8MB)
__device__ float g_cos[PP * BB];              // cosine sims
__device__ float g_htab[PP * VV * HH];        // tanh(tables@w1+b1) [512][42]

// ---------------- kernel 1: knorm — n[p,b,s]; tail: w1 transpose ----------------
__global__ __launch_bounds__(256) void knorm(const float* __restrict__ ctx,
                                             const float* __restrict__ lora,
                                             const float* __restrict__ w1) {
    __shared__ float su[PP * DD];
    int t = threadIdx.x, warp = t >> 5, lane = t & 31;
    for (int i = t; i < PP * DD; i += 256) {
        float e = lora[i];
        su[i] = e / fmaxf(2.0f * fabsf(e), EPSF);
    }
    __syncthreads();
    int row = blockIdx.x * 8 + warp;          // 1024 blocks x 8 warps = 8192 rows
    int b = row >> 11, s = row & 2047;
    const float4* x4 = reinterpret_cast<const float4*>(ctx + (size_t)row * DD);
    float nrm2 = 0.f;
    float dot[PP];
#pragma unroll
    for (int p = 0; p < PP; p++) dot[p] = 0.f;
#pragma unroll
    for (int it = 0; it < 8; it++) {
        int q = lane + it * 32;
        float4 x = x4[q];
        nrm2 += x.x * x.x + x.y * x.y + x.z * x.z + x.w * x.w;
#pragma unroll
        for (int p = 0; p < PP; p++) {
            float4 u = reinterpret_cast<const float4*>(su + p * DD)[q];
            dot[p] += x.x * u.x + x.y * u.y + x.z * u.z + x.w * u.w;
        }
    }
#pragma unroll
    for (int o = 16; o; o >>= 1) {
        nrm2 += __shfl_xor_sync(0xffffffffu, nrm2, o);
#pragma unroll
        for (int p = 0; p < PP; p++) dot[p] += __shfl_xor_sync(0xffffffffu, dot[p], o);
    }
    if (lane < PP) {
        float dl = 0.f;
#pragma unroll
        for (int p = 0; p < PP; p++) if (lane == p) dl = dot[p];
        float v = dl / fmaxf(sqrtf(nrm2), EPSF);
        float c = fmaxf(v, 0.f);
        g_n[((size_t)lane * BB + b) * SS + s] = c / fmaxf(SQRT_S * c, EPSF);
    }
    // tail: transpose w1 -> g_w1t  (168*256 = 43008 = D*H exactly)
    if (blockIdx.x < 168) {
        int idx = blockIdx.x * 256 + t;
        int d = idx / HH, h = idx - d * HH;
        g_w1t[(size_t)h * DD + d] = w1[idx];
    }
}

// ---------------- kernel 2: softmax over s (per p,b) -> weights ----------------
__global__ __launch_bounds__(256) void ksoft() {
    __shared__ float sn[SS];
    __shared__ float red[256];
    int pb = blockIdx.x;
    int t = threadIdx.x;
    const float* np = g_n + (size_t)pb * SS;
    float m = -1e30f;
    for (int i = t; i < SS; i += 256) { float v = np[i]; sn[i] = v; m = fmaxf(m, v); }
    red[t] = m; __syncthreads();
    for (int o = 128; o; o >>= 1) { if (t < o) red[t] = fmaxf(red[t], red[t + o]); __syncthreads(); }
    m = red[0]; __syncthreads();
    float sum = 0.f;
    for (int i = t; i < SS; i += 256) sum += expf(sn[i] - m);
    red[t] = sum; __syncthreads();
    for (int o = 128; o; o >>= 1) { if (t < o) red[t] += red[t + o]; __syncthreads(); }
    float inv = 1.0f / red[0];
    for (int i = t; i < SS; i += 256) g_wsm[(size_t)pb * SS + i] = expf(sn[i] - m) * inv;
}

// ---------------- kernel 3: a_v partials: sum_s w[p,b,s] * ctx[b,s,d] ----------------
__global__ __launch_bounds__(256) void kavp(const float* __restrict__ ctx) {
    __shared__ float ws[32 * PP];
    int schunk = blockIdx.x, b = blockIdx.y, dh = blockIdx.z;
    int t = threadIdx.x;
    ws[t] = g_wsm[((size_t)(t & 7) * BB + b) * SS + schunk * 32 + (t >> 3)];
    __syncthreads();
    float2 acc[PP];
#pragma unroll
    for (int p = 0; p < PP; p++) acc[p] = make_float2(0.f, 0.f);
    const float2* cp = reinterpret_cast<const float2*>(ctx) +
                       ((size_t)b * SS + schunk * 32) * 512 + dh * 256 + t;
#pragma unroll
    for (int sl = 0; sl < 32; sl += 8) {
        float2 x[8];
#pragma unroll
        for (int r = 0; r < 8; r++) x[r] = cp[(size_t)(sl + r) * 512];
#pragma unroll
        for (int p = 0; p < PP; p++) {
#pragma unroll
            for (int r = 0; r < 8; r++) {
                float w = ws[(sl + r) * 8 + p];
                acc[p].x += w * x[r].x;
                acc[p].y += w * x[r].y;
            }
        }
    }
#pragma unroll
    for (int p = 0; p < PP; p++)
        reinterpret_cast<float2*>(g_avp)[((size_t)(p * BB + b) * NSC + schunk) * 512 + dh * 256 + t] = acc[p];
}

// ---------------- kernel 4: kmid — avred+cos (blk<32) || htab (32<=blk<288) ----------------
__global__ __launch_bounds__(256) void kmid(const float* __restrict__ lora,
                                            const float* __restrict__ tables,
                                            const float* __restrict__ b1) {
    int blk = blockIdx.x;
    int t = threadIdx.x, warp = t >> 5, lane = t & 31;
    if (blk < 32) {
        __shared__ float red3[24];
        int pb = blk, p = pb >> 2;
        float dot = 0.f, an2 = 0.f, en2 = 0.f;
        for (int d = t; d < DD; d += 256) {
            float s = 0.f;
#pragma unroll 8
            for (int c = 0; c < NSC; c++) s += g_avp[((size_t)pb * NSC + c) * DD + d];
            float e = lora[p * DD + d];
            dot += e * s; an2 += s * s; en2 += e * e;
        }
#pragma unroll
        for (int o = 16; o; o >>= 1) {
            dot += __shfl_xor_sync(0xffffffffu, dot, o);
            an2 += __shfl_xor_sync(0xffffffffu, an2, o);
            en2 += __shfl_xor_sync(0xffffffffu, en2, o);
        }
        if (lane == 0) { red3[warp] = dot; red3[8 + warp] = an2; red3[16 + warp] = en2; }
        __syncthreads();
        if (t == 0) {
            float D = 0.f, A = 0.f, E = 0.f;
#pragma unroll
            for (int w = 0; w < 8; w++) { D += red3[w]; A += red3[8 + w]; E += red3[16 + w]; }
            g_cos[pb] = D / fmaxf(sqrtf(E) * sqrtf(A), COSEPS);
        }
    } else {
        __shared__ float tok[2 * DD];
        int pair = blk - 32;                       // rows 2*pair, 2*pair+1 of [512][D]
        const float* src = tables + (size_t)pair * 2 * DD;
        for (int i = t; i < 2 * DD; i += 256) tok[i] = src[i];
        __syncthreads();
#pragma unroll
        for (int j = 0; j < 6; j++) {
            int h = warp + j * 8;
            if (h < HH) {
                const float4* wr = reinterpret_cast<const float4*>(g_w1t + (size_t)h * DD);
                float d0 = 0.f, d1 = 0.f;
#pragma unroll
                for (int it = 0; it < 8; it++) {
                    int q = lane + it * 32;
                    float4 wv = wr[q];
                    float4 t0 = reinterpret_cast<const float4*>(tok)[q];
                    float4 t1 = reinterpret_cast<const float4*>(tok + DD)[q];
                    d0 += wv.x * t0.x + wv.y * t0.y + wv.z * t0.z + wv.w * t0.w;
                    d1 += wv.x * t1.x + wv.y * t1.y + wv.z * t1.z + wv.w * t1.w;
                }
#pragma unroll
                for (int o = 16; o; o >>= 1) {
                    d0 += __shfl_xor_sync(0xffffffffu, d0, o);
                    d1 += __shfl_xor_sync(0xffffffffu, d1, o);
                }
                if (lane == 0) {
                    float bh = b1[h];
                    g_htab[(size_t)(pair * 2 + 0) * HH + h] = tanhf(d0 + bh);
                    g_htab[(size_t)(pair * 2 + 1) * HH + h] = tanhf(d1 + bh);
                }
            }
        }
    }
}

// ---------------- kernel 5: kout — gates + hbar inline, then hbar @ w2 + b2 ----------------
__device__ __forceinline__ unsigned long long fma2(unsigned long long a,
                                                   unsigned long long b,
                                                   unsigned long long c) {
    unsigned long long d;
    asm("fma.rn.f32x2 %0, %1, %2, %3;" : "=l"(d) : "l"(a), "l"(b), "l"(c));
    return d;
}

// 64 rows per block (blockIdx.y of 4), 256 k per block (blockIdx.x of 192). 128 threads.
__global__ __launch_bounds__(128, 4) void kout(const int* __restrict__ prefix,
                                               const float* __restrict__ w2,
                                               const float* __restrict__ b2,
                                               float* __restrict__ out) {
    __shared__ float sgate[32];
    __shared__ unsigned long long hb2[64 * HH];   // hbar duplicated {v,v}, [row][h]
    int r0 = blockIdx.y * 64;
    int t = threadIdx.x;
    if (t < 32) {
        // double softmax over p for batch bq = t>>3; store gate for p = t&7
        int bq = t >> 3, p = t & 7;
        float x[PP], m = -1e30f;
#pragma unroll
        for (int pp = 0; pp < PP; pp++) { x[pp] = g_cos[pp * BB + bq]; m = fmaxf(m, x[pp]); }
        float z = 0.f;
#pragma unroll
        for (int pp = 0; pp < PP; pp++) { x[pp] = expf(x[pp] - m); z += x[pp]; }
#pragma unroll
        for (int pp = 0; pp < PP; pp++) x[pp] /= z;        // s_t
        m = -1e30f;
#pragma unroll
        for (int pp = 0; pp < PP; pp++) m = fmaxf(m, x[pp]);
        z = 0.f;
#pragma unroll
        for (int pp = 0; pp < PP; pp++) { x[pp] = expf(x[pp] - m); z += x[pp]; }
        sgate[t] = x[p] / z;                                // gate[bq][p]
    }
    __syncthreads();
    for (int i = t; i < 64 * HH; i += 128) {
        int r = i / HH, h = i - r * HH;
        int bv = r0 + r;
        int pf = prefix[bv];
        int bq = bv >> 6;
        float s = 0.f;
#pragma unroll
        for (int p = 0; p < PP; p++)
            s += sgate[bq * 8 + p] * g_htab[((size_t)p * VV + pf) * HH + h];
        float2 d2 = make_float2(s, s);
        hb2[i] = *reinterpret_cast<unsigned long long*>(&d2);
    }
    __syncthreads();
    int kp = blockIdx.x * 256 + t * 2;
    unsigned long long wcol[HH];
#pragma unroll
    for (int h = 0; h < HH; h++) {
        float2 wv = *reinterpret_cast<const float2*>(w2 + (size_t)h * KK + kp);
        wcol[h] = *reinterpret_cast<unsigned long long*>(&wv);
    }
    float2 bv2 = *reinterpret_cast<const float2*>(b2 + kp);
    unsigned long long binit = *reinterpret_cast<unsigned long long*>(&bv2);
    for (int rg = 0; rg < 64; rg += 4) {
        unsigned long long a0 = binit, a1 = binit, a2 = binit, a3 = binit;
#pragma unroll
        for (int h = 0; h < HH; h++) {
            a0 = fma2(wcol[h], hb2[(rg + 0) * HH + h], a0);
            a1 = fma2(wcol[h], hb2[(rg + 1) * HH + h], a1);
            a2 = fma2(wcol[h], hb2[(rg + 2) * HH + h], a2);
            a3 = fma2(wcol[h], hb2[(rg + 3) * HH + h], a3);
        }
        *reinterpret_cast<float2*>(out + (size_t)(r0 + rg + 0) * KK + kp) = *reinterpret_cast<float2*>(&a0);
        *reinterpret_cast<float2*>(out + (size_t)(r0 + rg + 1) * KK + kp) = *reinterpret_cast<float2*>(&a1);
        *reinterpret_cast<float2*>(out + (size_t)(r0 + rg + 2) * KK + kp) = *reinterpret_cast<float2*>(&a2);
        *reinterpret_cast<float2*>(out + (size_t)(r0 + rg + 3) * KK + kp) = *reinterpret_cast<float2*>(&a3);
    }
}

// ---------------- launcher ----------------
extern "C" void kernel_launch(void* const* d_in, const int* in_sizes, int n_in,
                              void* d_out, int out_size) {
    const int* prefix = nullptr;
    const float *ctx = nullptr, *tables = nullptr, *lora = nullptr;
    const float *w1 = nullptr, *b1 = nullptr, *w2 = nullptr, *b2 = nullptr;
    for (int i = 0; i < n_in; i++) {
        switch (in_sizes[i]) {
            case 256:     prefix = (const int*)d_in[i];   break;  // (B,V) int32
            case 8388608: ctx    = (const float*)d_in[i]; break;  // (B,S,D)
            case 524288:  tables = (const float*)d_in[i]; break;  // (P,V,D)
            case 8192:    lora   = (const float*)d_in[i]; break;  // (P,D)
            case 43008:   w1     = (const float*)d_in[i]; break;  // (D,H)
            case 42:      b1     = (const float*)d_in[i]; break;  // (H,)
            case 2064384: w2     = (const float*)d_in[i]; break;  // (H,K)
            case 49152:   b2     = (const float*)d_in[i]; break;  // (K,)
        }
    }
    float* out = (float*)d_out;

    knorm<<<1024, 256>>>(ctx, lora, w1);
    ksoft<<<32, 256>>>();
    kavp<<<dim3(NSC, 4, 2), 256>>>(ctx);
    kmid<<<288, 256>>>(lora, tables, b1);
    kout<<<dim3(192, 4), 128>>>(prefix, w2, b2, out);
}